// round 1
// baseline (speedup 1.0000x reference)
#include <cuda_runtime.h>
#include <cuda_bf16.h>

// MomentumLSTM: 2-layer LSTM (B=32768,T=60,D=7,H1=64,H2=32) + dense(16)+sigmoid head.
// One CTA = 32 batch elements, all 60 timesteps local. Weights transposed in SMEM (fp32),
// state h1/h2 kept duplicated in SMEM for f32x2 packed FMA (pair = unit dimension).

#define BATCH   32768
#define TT      60
#define DD      7
#define H1      64
#define G1      256
#define H2      32
#define G2      128
#define BT      32
#define NTHREADS 256
#define H1STRIDE 66   // padded row stride (floats) for sH1 to avoid STS bank conflicts
#define H2STRIDE 66

// SMEM float offsets
#define OFF_WIH1T 0                         // [7][256]
#define OFF_WHH1T 1792                      // [64][256]
#define OFF_W2T   18176                     // [96][128] (k<64: Wih2, k>=64: Whh2)
#define OFF_B1    30464                     // [256]
#define OFF_B2    30720                     // [128]
#define OFF_H1    30848                     // [64][66] dup: [k][2b],[2b+1] = h1[b][k]
#define OFF_H2    35072                     // [32][66] dup
#define OFF_X     37184                     // [32][60][7] raw x tile
#define SMEM_FLOATS 50624
#define SMEM_BYTES  (SMEM_FLOATS * 4)       // 202496

typedef unsigned long long u64t;

__device__ __forceinline__ u64t pk2(float a, float b) {
    u64t r; asm("mov.b64 %0, {%1, %2};" : "=l"(r) : "f"(a), "f"(b)); return r;
}
__device__ __forceinline__ void upk(u64t v, float& lo, float& hi) {
    asm("mov.b64 {%0, %1}, %2;" : "=f"(lo), "=f"(hi) : "l"(v));
}
__device__ __forceinline__ u64t fma2(u64t a, u64t b, u64t c) {
    u64t d; asm("fma.rn.f32x2 %0, %1, %2, %3;" : "=l"(d) : "l"(a), "l"(b), "l"(c)); return d;
}
__device__ __forceinline__ u64t lds64(const float* p) {
    return *reinterpret_cast<const u64t*>(p);
}
__device__ __forceinline__ void sts64(float* p, u64t v) {
    *reinterpret_cast<u64t*>(p) = v;
}
__device__ __forceinline__ float sigf(float x) {
    return __fdividef(1.0f, 1.0f + __expf(-x));
}
__device__ __forceinline__ float tanhf_(float x) {
    return __fdividef(2.0f, 1.0f + __expf(-2.0f * x)) - 1.0f;
}

__global__ void __launch_bounds__(NTHREADS, 1)
momentum_lstm_kernel(const float* __restrict__ x,
                     const float* __restrict__ Wih1, const float* __restrict__ Whh1,
                     const float* __restrict__ bih1, const float* __restrict__ bhh1,
                     const float* __restrict__ Wih2, const float* __restrict__ Whh2,
                     const float* __restrict__ bih2, const float* __restrict__ bhh2,
                     const float* __restrict__ Wd,  const float* __restrict__ bd,
                     const float* __restrict__ Wo,  const float* __restrict__ bo,
                     float* __restrict__ out)
{
    extern __shared__ float sm[];
    float* sWih1T = sm + OFF_WIH1T;
    float* sWhh1T = sm + OFF_WHH1T;
    float* sW2T   = sm + OFF_W2T;
    float* sB1    = sm + OFF_B1;
    float* sB2    = sm + OFF_B2;
    float* sH1    = sm + OFF_H1;
    float* sH2    = sm + OFF_H2;
    float* sX     = sm + OFF_X;

    const int tid  = threadIdx.x;
    const int lane = tid & 31;
    const int wrp  = tid >> 5;
    const int bbase = blockIdx.x * BT;

    // ---------- stage weights (transposed), biases, zero state, stage x tile ----------
    for (int i = tid; i < DD * G1; i += NTHREADS) {
        int d = i >> 8, g = i & 255;
        sWih1T[i] = Wih1[g * DD + d];
    }
    for (int i = tid; i < H1 * G1; i += NTHREADS) {
        int k = i >> 8, g = i & 255;
        sWhh1T[i] = Whh1[g * H1 + k];
    }
    for (int i = tid; i < (H1 + H2) * G2; i += NTHREADS) {
        int k = i >> 7, g = i & 127;
        sW2T[i] = (k < H1) ? Wih2[g * H1 + k] : Whh2[g * H2 + (k - H1)];
    }
    sB1[tid] = bih1[tid] + bhh1[tid];              // NTHREADS == G1
    if (tid < G2) sB2[tid] = bih2[tid] + bhh2[tid];
    for (int i = tid; i < H1 * H1STRIDE; i += NTHREADS) sH1[i] = 0.0f;
    for (int i = tid; i < H2 * H2STRIDE; i += NTHREADS) sH2[i] = 0.0f;
    {
        const float4* xsrc = reinterpret_cast<const float4*>(x + (size_t)bbase * (TT * DD));
        float4* xdst = reinterpret_cast<float4*>(sX);
        #pragma unroll 4
        for (int i = tid; i < BT * TT * DD / 4; i += NTHREADS) xdst[i] = xsrc[i];
    }
    __syncthreads();

    // ---------- thread tilings ----------
    // layer1: 32 unit-pairs x 8 batch-groups(4 each). warp spans 8 iu x 4 ib.
    const int iu  = (wrp & 3) * 8 + (lane & 7);    // 0..31
    const int ib  = (wrp >> 2) * 4 + (lane >> 3);  // 0..7
    const int u0  = 2 * iu;
    const int b01 = 4 * ib;
    // layer2: 16 unit-pairs x 16 batch-groups(2 each). warp spans 4 iu2 x 8 ib2.
    const int iu2 = (wrp & 3) * 4 + (lane & 3);    // 0..15
    const int ib2 = (wrp >> 2) * 8 + (lane >> 2);  // 0..15
    const int u02 = 2 * iu2;
    const int b02 = 2 * ib2;

    float c1[4][2];
    #pragma unroll
    for (int b = 0; b < 4; b++) { c1[b][0] = 0.0f; c1[b][1] = 0.0f; }
    float c2[2][2];
    c2[0][0] = c2[0][1] = c2[1][0] = c2[1][1] = 0.0f;

    const u64t bia1_0 = lds64(&sB1[0 * H1 + u0]);
    const u64t bia1_1 = lds64(&sB1[1 * H1 + u0]);
    const u64t bia1_2 = lds64(&sB1[2 * H1 + u0]);
    const u64t bia1_3 = lds64(&sB1[3 * H1 + u0]);
    const u64t bia2_0 = lds64(&sB2[0 * H2 + u02]);
    const u64t bia2_1 = lds64(&sB2[1 * H2 + u02]);
    const u64t bia2_2 = lds64(&sB2[2 * H2 + u02]);
    const u64t bia2_3 = lds64(&sB2[3 * H2 + u02]);

    for (int t = 0; t < TT; t++) {
        // ================= layer 1 gates =================
        u64t a1[4][4];
        #pragma unroll
        for (int b = 0; b < 4; b++) {
            a1[0][b] = bia1_0; a1[1][b] = bia1_1; a1[2][b] = bia1_2; a1[3][b] = bia1_3;
        }
        // input projection (D=7)
        #pragma unroll
        for (int d = 0; d < DD; d++) {
            u64t w0 = lds64(&sWih1T[d * G1 + 0 * H1 + u0]);
            u64t w1 = lds64(&sWih1T[d * G1 + 1 * H1 + u0]);
            u64t w2 = lds64(&sWih1T[d * G1 + 2 * H1 + u0]);
            u64t w3 = lds64(&sWih1T[d * G1 + 3 * H1 + u0]);
            #pragma unroll
            for (int b = 0; b < 4; b++) {
                float xv = sX[(b01 + b) * (TT * DD) + t * DD + d];
                u64t xp = pk2(xv, xv);
                a1[0][b] = fma2(w0, xp, a1[0][b]);
                a1[1][b] = fma2(w1, xp, a1[1][b]);
                a1[2][b] = fma2(w2, xp, a1[2][b]);
                a1[3][b] = fma2(w3, xp, a1[3][b]);
            }
        }
        // hidden projection (K=64)
        #pragma unroll 4
        for (int k = 0; k < H1; k++) {
            u64t w0 = lds64(&sWhh1T[k * G1 + 0 * H1 + u0]);
            u64t w1 = lds64(&sWhh1T[k * G1 + 1 * H1 + u0]);
            u64t w2 = lds64(&sWhh1T[k * G1 + 2 * H1 + u0]);
            u64t w3 = lds64(&sWhh1T[k * G1 + 3 * H1 + u0]);
            #pragma unroll
            for (int b = 0; b < 4; b++) {
                u64t hv = lds64(&sH1[k * H1STRIDE + 2 * (b01 + b)]);
                a1[0][b] = fma2(w0, hv, a1[0][b]);
                a1[1][b] = fma2(w1, hv, a1[1][b]);
                a1[2][b] = fma2(w2, hv, a1[2][b]);
                a1[3][b] = fma2(w3, hv, a1[3][b]);
            }
        }
        __syncthreads();   // all reads of old sH1 done

        // pointwise layer1 + write new h1 (duplicated)
        #pragma unroll
        for (int b = 0; b < 4; b++) {
            float iv[2], fv[2], gv[2], ov[2];
            upk(a1[0][b], iv[0], iv[1]);
            upk(a1[1][b], fv[0], fv[1]);
            upk(a1[2][b], gv[0], gv[1]);
            upk(a1[3][b], ov[0], ov[1]);
            #pragma unroll
            for (int u = 0; u < 2; u++) {
                float ii = sigf(iv[u]);
                float ff = sigf(fv[u]);
                float gg = tanhf_(gv[u]);
                float oo = sigf(ov[u]);
                float cc = ff * c1[b][u] + ii * gg;
                c1[b][u] = cc;
                float hh = oo * tanhf_(cc);
                sts64(&sH1[(u0 + u) * H1STRIDE + 2 * (b01 + b)], pk2(hh, hh));
            }
        }
        __syncthreads();   // new sH1 visible

        // ================= layer 2 gates =================
        u64t a2[4][2];
        a2[0][0] = bia2_0; a2[1][0] = bia2_1; a2[2][0] = bia2_2; a2[3][0] = bia2_3;
        a2[0][1] = bia2_0; a2[1][1] = bia2_1; a2[2][1] = bia2_2; a2[3][1] = bia2_3;
        #pragma unroll 4
        for (int k = 0; k < H1; k++) {       // input = new h1
            u64t w0 = lds64(&sW2T[k * G2 + 0 * H2 + u02]);
            u64t w1 = lds64(&sW2T[k * G2 + 1 * H2 + u02]);
            u64t w2 = lds64(&sW2T[k * G2 + 2 * H2 + u02]);
            u64t w3 = lds64(&sW2T[k * G2 + 3 * H2 + u02]);
            #pragma unroll
            for (int b = 0; b < 2; b++) {
                u64t hv = lds64(&sH1[k * H1STRIDE + 2 * (b02 + b)]);
                a2[0][b] = fma2(w0, hv, a2[0][b]);
                a2[1][b] = fma2(w1, hv, a2[1][b]);
                a2[2][b] = fma2(w2, hv, a2[2][b]);
                a2[3][b] = fma2(w3, hv, a2[3][b]);
            }
        }
        #pragma unroll 4
        for (int k = 0; k < H2; k++) {       // recurrent = old h2
            u64t w0 = lds64(&sW2T[(H1 + k) * G2 + 0 * H2 + u02]);
            u64t w1 = lds64(&sW2T[(H1 + k) * G2 + 1 * H2 + u02]);
            u64t w2 = lds64(&sW2T[(H1 + k) * G2 + 2 * H2 + u02]);
            u64t w3 = lds64(&sW2T[(H1 + k) * G2 + 3 * H2 + u02]);
            #pragma unroll
            for (int b = 0; b < 2; b++) {
                u64t hv = lds64(&sH2[k * H2STRIDE + 2 * (b02 + b)]);
                a2[0][b] = fma2(w0, hv, a2[0][b]);
                a2[1][b] = fma2(w1, hv, a2[1][b]);
                a2[2][b] = fma2(w2, hv, a2[2][b]);
                a2[3][b] = fma2(w3, hv, a2[3][b]);
            }
        }
        __syncthreads();   // all reads of old sH2 done

        // pointwise layer2 + write new h2 (duplicated)
        #pragma unroll
        for (int b = 0; b < 2; b++) {
            float iv[2], fv[2], gv[2], ov[2];
            upk(a2[0][b], iv[0], iv[1]);
            upk(a2[1][b], fv[0], fv[1]);
            upk(a2[2][b], gv[0], gv[1]);
            upk(a2[3][b], ov[0], ov[1]);
            #pragma unroll
            for (int u = 0; u < 2; u++) {
                float ii = sigf(iv[u]);
                float ff = sigf(fv[u]);
                float gg = tanhf_(gv[u]);
                float oo = sigf(ov[u]);
                float cc = ff * c2[b][u] + ii * gg;
                c2[b][u] = cc;
                float hh = oo * tanhf_(cc);
                sts64(&sH2[(u02 + u) * H2STRIDE + 2 * (b02 + b)], pk2(hh, hh));
            }
        }
        __syncthreads();   // new sH2 visible
    }

    // ================= head: dense(16)+relu -> dot(16)+sigmoid =================
    if (tid < BT) {
        const int b = tid;
        float o = __ldg(&bo[0]);
        #pragma unroll
        for (int j = 0; j < 16; j++) {
            float s = __ldg(&bd[j]);
            #pragma unroll
            for (int k = 0; k < H2; k++) {
                s += sH2[k * H2STRIDE + 2 * b] * __ldg(&Wd[j * H2 + k]);
            }
            o += fmaxf(s, 0.0f) * __ldg(&Wo[j]);
        }
        out[bbase + b] = sigf(o);
    }
}

extern "C" void kernel_launch(void* const* d_in, const int* in_sizes, int n_in,
                              void* d_out, int out_size) {
    const float* x    = (const float*)d_in[0];
    const float* Wih1 = (const float*)d_in[1];
    const float* Whh1 = (const float*)d_in[2];
    const float* bih1 = (const float*)d_in[3];
    const float* bhh1 = (const float*)d_in[4];
    const float* Wih2 = (const float*)d_in[5];
    const float* Whh2 = (const float*)d_in[6];
    const float* bih2 = (const float*)d_in[7];
    const float* bhh2 = (const float*)d_in[8];
    const float* Wd   = (const float*)d_in[9];
    const float* bd   = (const float*)d_in[10];
    const float* Wo   = (const float*)d_in[11];
    const float* bo   = (const float*)d_in[12];
    float* out = (float*)d_out;

    static bool attr_set = false;
    if (!attr_set) {
        cudaFuncSetAttribute(momentum_lstm_kernel,
                             cudaFuncAttributeMaxDynamicSharedMemorySize, SMEM_BYTES);
        attr_set = true;
    }

    momentum_lstm_kernel<<<BATCH / BT, NTHREADS, SMEM_BYTES>>>(
        x, Wih1, Whh1, bih1, bhh1, Wih2, Whh2, bih2, bhh2, Wd, bd, Wo, bo, out);
}

// round 2
// speedup vs baseline: 1.4402x; 1.4402x over previous
#include <cuda_runtime.h>
#include <cuda_bf16.h>

// MomentumLSTM v2: batch-paired f32x2, broadcast h loads, BT=128/CTA.
// Layer1: thread = 2 units x 4 gates x 16 batches (8 pairs).
// Layer2: thread = 2 units x 4 gates x 8 batches (4 pairs).

#define BATCH 32768
#define TT    60
#define DD    7
#define H1    64
#define G1    256
#define H2    32
#define G2    128
#define BT    128
#define NT    256
#define HS    130            // padded batch stride for sH1/sH2 (floats)

// SMEM float offsets
#define OFF_W1T 0                          // [71][256]  rows 0..6 = x-weights, 7..70 = h-weights
#define OFF_W2T 18176                      // [96][128]  rows 0..63 = Wih2(k), 64..95 = Whh2(k)
#define OFF_B1  30464                      // [256]
#define OFF_B2  30720                      // [128]
#define OFF_H1  30848                      // [64][HS]
#define OFF_H2  39168                      // [32][HS]
#define OFF_X   43328                      // [2][7][128]
#define SMEM_FLOATS 45120
#define SMEM_BYTES  (SMEM_FLOATS * 4)      // 180480

typedef unsigned long long u64t;

__device__ __forceinline__ u64t pk2(float a, float b) {
    u64t r; asm("mov.b64 %0, {%1, %2};" : "=l"(r) : "f"(a), "f"(b)); return r;
}
__device__ __forceinline__ void upk(u64t v, float& lo, float& hi) {
    asm("mov.b64 {%0, %1}, %2;" : "=f"(lo), "=f"(hi) : "l"(v));
}
__device__ __forceinline__ u64t fma2(u64t a, u64t b, u64t c) {
    u64t d; asm("fma.rn.f32x2 %0, %1, %2, %3;" : "=l"(d) : "l"(a), "l"(b), "l"(c)); return d;
}
__device__ __forceinline__ u64t lds64(const float* p) {
    return *reinterpret_cast<const u64t*>(p);
}
__device__ __forceinline__ void sts64(float* p, u64t v) {
    *reinterpret_cast<u64t*>(p) = v;
}
__device__ __forceinline__ float sigf(float x) {
    return __fdividef(1.0f, 1.0f + __expf(-x));
}
__device__ __forceinline__ float tanhf_(float x) {
    return __fdividef(2.0f, 1.0f + __expf(-2.0f * x)) - 1.0f;
}

__global__ void __launch_bounds__(NT, 1)
momentum_lstm_kernel(const float* __restrict__ x,
                     const float* __restrict__ Wih1, const float* __restrict__ Whh1,
                     const float* __restrict__ bih1, const float* __restrict__ bhh1,
                     const float* __restrict__ Wih2, const float* __restrict__ Whh2,
                     const float* __restrict__ bih2, const float* __restrict__ bhh2,
                     const float* __restrict__ Wd,  const float* __restrict__ bd,
                     const float* __restrict__ Wo,  const float* __restrict__ bo,
                     float* __restrict__ out)
{
    extern __shared__ float sm[];
    float* sW1T = sm + OFF_W1T;
    float* sW2T = sm + OFF_W2T;
    float* sB1  = sm + OFF_B1;
    float* sB2  = sm + OFF_B2;
    float* sH1  = sm + OFF_H1;
    float* sH2  = sm + OFF_H2;
    float* sX   = sm + OFF_X;

    const int tid   = threadIdx.x;
    const int bbase = blockIdx.x * BT;

    // ---------------- stage weights (transposed) ----------------
    for (int i = tid; i < DD * G1; i += NT) {          // x-weights rows 0..6
        int d = i >> 8, g = i & 255;
        sW1T[d * G1 + g] = Wih1[g * DD + d];
    }
    for (int i = tid; i < H1 * G1; i += NT) {          // h-weights rows 7..70
        int k = i >> 8, g = i & 255;
        sW1T[(DD + k) * G1 + g] = Whh1[g * H1 + k];
    }
    for (int i = tid; i < (H1 + H2) * G2; i += NT) {
        int k = i >> 7, g = i & 127;
        sW2T[i] = (k < H1) ? Wih2[g * H1 + k] : Whh2[g * H2 + (k - H1)];
    }
    sB1[tid] = bih1[tid] + bhh1[tid];
    if (tid < G2) sB2[tid] = bih2[tid] + bhh2[tid];
    for (int i = tid; i < H1 * HS; i += NT) sH1[i] = 0.0f;
    for (int i = tid; i < H2 * HS; i += NT) sH2[i] = 0.0f;

    // ---------------- thread tilings ----------------
    const int u01 = 2 * (tid & 31);        // layer1 unit pair base (0..62)
    const int b1  = (tid >> 5) * 16;       // layer1 batch base (warp = batch group)
    const int u02 = 2 * (tid & 15);        // layer2 unit pair base (0..30)
    const int b2  = (tid >> 4) * 8;        // layer2 batch base

    float c1[2][16];
    #pragma unroll
    for (int u = 0; u < 2; u++)
        #pragma unroll
        for (int b = 0; b < 16; b++) c1[u][b] = 0.0f;
    float c2[2][8];
    #pragma unroll
    for (int u = 0; u < 2; u++)
        #pragma unroll
        for (int b = 0; b < 8; b++) c2[u][b] = 0.0f;

    // ---------------- prefetch x for t=0 ----------------
    float xr[4];
    #pragma unroll
    for (int j = 0; j < 4; j++) {
        int idx = tid + NT * j;
        if (j < 3 || tid < BT * DD - 3 * NT) {
            int b = idx / DD, d = idx - b * DD;
            xr[j] = x[(bbase + b) * (TT * DD) + 0 * DD + d];
        }
    }
    __syncthreads();

    for (int t = 0; t < TT; t++) {
        float* sXb = sX + (t & 1) * (DD * BT);
        // store prefetched x_t, then prefetch x_{t+1}
        #pragma unroll
        for (int j = 0; j < 4; j++) {
            int idx = tid + NT * j;
            if (j < 3 || tid < BT * DD - 3 * NT) {
                int b = idx / DD, d = idx - b * DD;
                sXb[d * BT + b] = xr[j];
            }
        }
        if (t + 1 < TT) {
            #pragma unroll
            for (int j = 0; j < 4; j++) {
                int idx = tid + NT * j;
                if (j < 3 || tid < BT * DD - 3 * NT) {
                    int b = idx / DD, d = idx - b * DD;
                    xr[j] = x[(bbase + b) * (TT * DD) + (t + 1) * DD + d];
                }
            }
        }
        __syncthreads();   // A: x_t + h2(t-1) visible

        // ================= layer 1 gates =================
        u64t a1[2][4][8];
        #pragma unroll
        for (int g = 0; g < 4; g++) {
            float blo = sB1[g * H1 + u01];
            float bhi = sB1[g * H1 + u01 + 1];
            u64t plo = pk2(blo, blo), phi = pk2(bhi, bhi);
            #pragma unroll
            for (int p = 0; p < 8; p++) { a1[0][g][p] = plo; a1[1][g][p] = phi; }
        }
        // x projection (rows 0..6 read sXb)
        #pragma unroll
        for (int d = 0; d < DD; d++) {
            u64t wp[2][4];
            #pragma unroll
            for (int g = 0; g < 4; g++) {
                u64t wv = lds64(&sW1T[d * G1 + g * H1 + u01]);
                float wl, wh; upk(wv, wl, wh);
                wp[0][g] = pk2(wl, wl); wp[1][g] = pk2(wh, wh);
            }
            #pragma unroll
            for (int p = 0; p < 8; p++) {
                u64t xv = lds64(&sXb[d * BT + b1 + 2 * p]);
                #pragma unroll
                for (int g = 0; g < 4; g++) {
                    a1[0][g][p] = fma2(wp[0][g], xv, a1[0][g][p]);
                    a1[1][g][p] = fma2(wp[1][g], xv, a1[1][g][p]);
                }
            }
        }
        // h projection (rows 7..70 read sH1)
        #pragma unroll 2
        for (int k = 0; k < H1; k++) {
            u64t wp[2][4];
            #pragma unroll
            for (int g = 0; g < 4; g++) {
                u64t wv = lds64(&sW1T[(DD + k) * G1 + g * H1 + u01]);
                float wl, wh; upk(wv, wl, wh);
                wp[0][g] = pk2(wl, wl); wp[1][g] = pk2(wh, wh);
            }
            #pragma unroll
            for (int p = 0; p < 8; p++) {
                u64t hv = lds64(&sH1[k * HS + b1 + 2 * p]);
                #pragma unroll
                for (int g = 0; g < 4; g++) {
                    a1[0][g][p] = fma2(wp[0][g], hv, a1[0][g][p]);
                    a1[1][g][p] = fma2(wp[1][g], hv, a1[1][g][p]);
                }
            }
        }
        __syncthreads();   // B: all reads of old sH1 done

        // pointwise layer1 + write new h1
        #pragma unroll
        for (int u = 0; u < 2; u++) {
            #pragma unroll
            for (int p = 0; p < 8; p++) {
                float gi[2], gf[2], gg[2], go[2], hh[2];
                upk(a1[u][0][p], gi[0], gi[1]);
                upk(a1[u][1][p], gf[0], gf[1]);
                upk(a1[u][2][p], gg[0], gg[1]);
                upk(a1[u][3][p], go[0], go[1]);
                #pragma unroll
                for (int s = 0; s < 2; s++) {
                    float ii = sigf(gi[s]);
                    float ff = sigf(gf[s]);
                    float g_ = tanhf_(gg[s]);
                    float oo = sigf(go[s]);
                    float cc = ff * c1[u][2 * p + s] + ii * g_;
                    c1[u][2 * p + s] = cc;
                    hh[s] = oo * tanhf_(cc);
                }
                sts64(&sH1[(u01 + u) * HS + b1 + 2 * p], pk2(hh[0], hh[1]));
            }
        }
        __syncthreads();   // C: new sH1 visible

        // ================= layer 2 gates =================
        u64t a2[2][4][4];
        #pragma unroll
        for (int g = 0; g < 4; g++) {
            float blo = sB2[g * H2 + u02];
            float bhi = sB2[g * H2 + u02 + 1];
            u64t plo = pk2(blo, blo), phi = pk2(bhi, bhi);
            #pragma unroll
            for (int p = 0; p < 4; p++) { a2[0][g][p] = plo; a2[1][g][p] = phi; }
        }
        #pragma unroll 2
        for (int k = 0; k < H1; k++) {       // input = new h1
            u64t wp[2][4];
            #pragma unroll
            for (int g = 0; g < 4; g++) {
                u64t wv = lds64(&sW2T[k * G2 + g * H2 + u02]);
                float wl, wh; upk(wv, wl, wh);
                wp[0][g] = pk2(wl, wl); wp[1][g] = pk2(wh, wh);
            }
            #pragma unroll
            for (int p = 0; p < 4; p++) {
                u64t hv = lds64(&sH1[k * HS + b2 + 2 * p]);
                #pragma unroll
                for (int g = 0; g < 4; g++) {
                    a2[0][g][p] = fma2(wp[0][g], hv, a2[0][g][p]);
                    a2[1][g][p] = fma2(wp[1][g], hv, a2[1][g][p]);
                }
            }
        }
        #pragma unroll 2
        for (int k = 0; k < H2; k++) {       // recurrent = old h2
            u64t wp[2][4];
            #pragma unroll
            for (int g = 0; g < 4; g++) {
                u64t wv = lds64(&sW2T[(H1 + k) * G2 + g * H2 + u02]);
                float wl, wh; upk(wv, wl, wh);
                wp[0][g] = pk2(wl, wl); wp[1][g] = pk2(wh, wh);
            }
            #pragma unroll
            for (int p = 0; p < 4; p++) {
                u64t hv = lds64(&sH2[k * HS + b2 + 2 * p]);
                #pragma unroll
                for (int g = 0; g < 4; g++) {
                    a2[0][g][p] = fma2(wp[0][g], hv, a2[0][g][p]);
                    a2[1][g][p] = fma2(wp[1][g], hv, a2[1][g][p]);
                }
            }
        }
        __syncthreads();   // D: all reads of old sH2 done

        // pointwise layer2 + write new h2
        #pragma unroll
        for (int u = 0; u < 2; u++) {
            #pragma unroll
            for (int p = 0; p < 4; p++) {
                float gi[2], gf[2], gg[2], go[2], hh[2];
                upk(a2[u][0][p], gi[0], gi[1]);
                upk(a2[u][1][p], gf[0], gf[1]);
                upk(a2[u][2][p], gg[0], gg[1]);
                upk(a2[u][3][p], go[0], go[1]);
                #pragma unroll
                for (int s = 0; s < 2; s++) {
                    float ii = sigf(gi[s]);
                    float ff = sigf(gf[s]);
                    float g_ = tanhf_(gg[s]);
                    float oo = sigf(go[s]);
                    float cc = ff * c2[u][2 * p + s] + ii * g_;
                    c2[u][2 * p + s] = cc;
                    hh[s] = oo * tanhf_(cc);
                }
                sts64(&sH2[(u02 + u) * HS + b2 + 2 * p], pk2(hh[0], hh[1]));
            }
        }
        // no sync here: sync A at top of next iter orders h2 writes before reads
    }
    __syncthreads();

    // ================= head: dense(16)+relu -> dot(16)+sigmoid =================
    if (tid < BT) {
        const int b = tid;
        float hv[H2];
        #pragma unroll
        for (int k = 0; k < H2; k++) hv[k] = sH2[k * HS + b];
        float o = __ldg(&bo[0]);
        #pragma unroll
        for (int j = 0; j < 16; j++) {
            float s = __ldg(&bd[j]);
            #pragma unroll
            for (int k = 0; k < H2; k++) s += hv[k] * __ldg(&Wd[j * H2 + k]);
            o += fmaxf(s, 0.0f) * __ldg(&Wo[j]);
        }
        out[bbase + b] = sigf(o);
    }
}

extern "C" void kernel_launch(void* const* d_in, const int* in_sizes, int n_in,
                              void* d_out, int out_size) {
    const float* x    = (const float*)d_in[0];
    const float* Wih1 = (const float*)d_in[1];
    const float* Whh1 = (const float*)d_in[2];
    const float* bih1 = (const float*)d_in[3];
    const float* bhh1 = (const float*)d_in[4];
    const float* Wih2 = (const float*)d_in[5];
    const float* Whh2 = (const float*)d_in[6];
    const float* bih2 = (const float*)d_in[7];
    const float* bhh2 = (const float*)d_in[8];
    const float* Wd   = (const float*)d_in[9];
    const float* bd   = (const float*)d_in[10];
    const float* Wo   = (const float*)d_in[11];
    const float* bo   = (const float*)d_in[12];
    float* out = (float*)d_out;

    static bool attr_set = false;
    if (!attr_set) {
        cudaFuncSetAttribute(momentum_lstm_kernel,
                             cudaFuncAttributeMaxDynamicSharedMemorySize, SMEM_BYTES);
        attr_set = true;
    }

    momentum_lstm_kernel<<<BATCH / BT, NT, SMEM_BYTES>>>(
        x, Wih1, Whh1, bih1, bhh1, Wih2, Whh2, bih2, bhh2, Wd, bd, Wo, bo, out);
}

// round 4
// speedup vs baseline: 1.5107x; 1.0490x over previous
#include <cuda_runtime.h>
#include <cuda_bf16.h>

// MomentumLSTM v4: warp-local recurrence (no __syncthreads in loop), EVEN slab stride 18
// (v3 failed: odd stride 17 broke 8B alignment of LDS.64/STS.64).
// Layer1: thread = 2 units(lanes span 64) x 4 gates x 8 batch-pairs.
// Layer2: thread = 2 units(16 lanes span 32) x 4 gates x 4 batch-pairs, half-warp batch split.

#define BATCH 32768
#define TT    60
#define DD    7
#define H1    64
#define G1    256
#define H2    32
#define G2    128
#define BT    128
#define NT    256
#define HS1   18             // EVEN padded stride: [64][18] per-warp h1 slab
#define HS2   18             // [32][18] per-warp h2 slab
#define XS    16             // [7][16] per-warp x slab

// SMEM float offsets
#define OFF_W1T 0                          // [71][256] rows 0..6 x-weights, 7..70 h-weights
#define OFF_W2T 18176                      // [96][128]
#define OFF_B1  30464                      // [256]
#define OFF_B2  30720                      // [128]
#define OFF_H1  30848                      // 8 warps x [64][18] = 9216
#define OFF_H2  40064                      // 8 warps x [32][18] = 4608
#define OFF_X   44672                      // 8 warps x [7][16]  = 896
#define SMEM_FLOATS 45568
#define SMEM_BYTES  (SMEM_FLOATS * 4)      // 182272

typedef unsigned long long u64t;

__device__ __forceinline__ u64t pk2(float a, float b) {
    u64t r; asm("mov.b64 %0, {%1, %2};" : "=l"(r) : "f"(a), "f"(b)); return r;
}
__device__ __forceinline__ void upk(u64t v, float& lo, float& hi) {
    asm("mov.b64 {%0, %1}, %2;" : "=f"(lo), "=f"(hi) : "l"(v));
}
__device__ __forceinline__ u64t fma2(u64t a, u64t b, u64t c) {
    u64t d; asm("fma.rn.f32x2 %0, %1, %2, %3;" : "=l"(d) : "l"(a), "l"(b), "l"(c)); return d;
}
__device__ __forceinline__ u64t lds64(const float* p) {
    return *reinterpret_cast<const u64t*>(p);
}
__device__ __forceinline__ void sts64(float* p, u64t v) {
    *reinterpret_cast<u64t*>(p) = v;
}
__device__ __forceinline__ float sigf(float x) {
    return __fdividef(1.0f, 1.0f + __expf(-x));
}
__device__ __forceinline__ float tanhf_(float x) {
    return __fdividef(2.0f, 1.0f + __expf(-2.0f * x)) - 1.0f;
}

__global__ void __launch_bounds__(NT, 1)
momentum_lstm_kernel(const float* __restrict__ x,
                     const float* __restrict__ Wih1, const float* __restrict__ Whh1,
                     const float* __restrict__ bih1, const float* __restrict__ bhh1,
                     const float* __restrict__ Wih2, const float* __restrict__ Whh2,
                     const float* __restrict__ bih2, const float* __restrict__ bhh2,
                     const float* __restrict__ Wd,  const float* __restrict__ bd,
                     const float* __restrict__ Wo,  const float* __restrict__ bo,
                     float* __restrict__ out)
{
    extern __shared__ float sm[];
    float* sW1T = sm + OFF_W1T;
    float* sW2T = sm + OFF_W2T;
    float* sB1  = sm + OFF_B1;
    float* sB2  = sm + OFF_B2;

    const int tid   = threadIdx.x;
    const int lane  = tid & 31;
    const int wid   = tid >> 5;
    const int bbase = blockIdx.x * BT;

    // per-warp smem slabs
    float* sH1w = sm + OFF_H1 + wid * (H1 * HS1);
    float* sH2w = sm + OFF_H2 + wid * (H2 * HS2);
    float* sXw  = sm + OFF_X  + wid * (DD * XS);

    // ---------------- cooperative staging (only global sync here) ----------------
    for (int i = tid; i < DD * G1; i += NT) {          // x-weights rows 0..6
        int d = i >> 8, g = i & 255;
        sW1T[d * G1 + g] = Wih1[g * DD + d];
    }
    for (int i = tid; i < H1 * G1; i += NT) {          // h-weights rows 7..70
        int k = i >> 8, g = i & 255;
        sW1T[(DD + k) * G1 + g] = Whh1[g * H1 + k];
    }
    for (int i = tid; i < (H1 + H2) * G2; i += NT) {
        int k = i >> 7, g = i & 127;
        sW2T[i] = (k < H1) ? Wih2[g * H1 + k] : Whh2[g * H2 + (k - H1)];
    }
    sB1[tid] = bih1[tid] + bhh1[tid];
    if (tid < G2) sB2[tid] = bih2[tid] + bhh2[tid];
    for (int i = lane; i < H1 * HS1; i += 32) sH1w[i] = 0.0f;
    for (int i = lane; i < H2 * HS2; i += 32) sH2w[i] = 0.0f;
    __syncthreads();

    // ---------------- thread tilings (all warp-local) ----------------
    const int u01 = 2 * lane;               // layer1: lanes span 64 units
    const int u02 = 2 * (lane & 15);        // layer2: 16 lanes span 32 units
    const int bh2 = (lane >> 4) * 8;        // layer2: half-warp batch split
    const float* xg = x + (size_t)(bbase + wid * 16) * (TT * DD);

    float c1[2][16];
    #pragma unroll
    for (int u = 0; u < 2; u++)
        #pragma unroll
        for (int b = 0; b < 16; b++) c1[u][b] = 0.0f;
    float c2[2][8];
    #pragma unroll
    for (int u = 0; u < 2; u++)
        #pragma unroll
        for (int b = 0; b < 8; b++) c2[u][b] = 0.0f;

    // prefetch x(t=0): warp loads its 16 batches x 7 dims (112 floats)
    float xr[4];
    #pragma unroll
    for (int j = 0; j < 4; j++) {
        int idx = 32 * j + lane;
        if (idx < DD * 16) {
            int b = idx / DD, d = idx - b * DD;
            xr[j] = xg[b * (TT * DD) + d];
        }
    }

    for (int t = 0; t < TT; t++) {
        // store prefetched x(t) into warp slab; prefetch x(t+1)
        #pragma unroll
        for (int j = 0; j < 4; j++) {
            int idx = 32 * j + lane;
            if (idx < DD * 16) {
                int b = idx / DD, d = idx - b * DD;
                sXw[d * XS + b] = xr[j];
            }
        }
        __syncwarp();                          // x(t) visible warp-wide
        if (t + 1 < TT) {
            #pragma unroll
            for (int j = 0; j < 4; j++) {
                int idx = 32 * j + lane;
                if (idx < DD * 16) {
                    int b = idx / DD, d = idx - b * DD;
                    xr[j] = xg[b * (TT * DD) + (t + 1) * DD + d];
                }
            }
        }

        // ================= layer 1 gates =================
        u64t a1[2][4][8];
        #pragma unroll
        for (int g = 0; g < 4; g++) {
            float blo = sB1[g * H1 + u01];
            float bhi = sB1[g * H1 + u01 + 1];
            u64t plo = pk2(blo, blo), phi = pk2(bhi, bhi);
            #pragma unroll
            for (int p = 0; p < 8; p++) { a1[0][g][p] = plo; a1[1][g][p] = phi; }
        }
        #pragma unroll
        for (int d = 0; d < DD; d++) {
            u64t wp[2][4];
            #pragma unroll
            for (int g = 0; g < 4; g++) {
                u64t wv = lds64(&sW1T[d * G1 + g * H1 + u01]);
                float wl, wh; upk(wv, wl, wh);
                wp[0][g] = pk2(wl, wl); wp[1][g] = pk2(wh, wh);
            }
            #pragma unroll
            for (int p = 0; p < 8; p++) {
                u64t xv = lds64(&sXw[d * XS + 2 * p]);
                #pragma unroll
                for (int g = 0; g < 4; g++) {
                    a1[0][g][p] = fma2(wp[0][g], xv, a1[0][g][p]);
                    a1[1][g][p] = fma2(wp[1][g], xv, a1[1][g][p]);
                }
            }
        }
        #pragma unroll 2
        for (int k = 0; k < H1; k++) {
            u64t wp[2][4];
            #pragma unroll
            for (int g = 0; g < 4; g++) {
                u64t wv = lds64(&sW1T[(DD + k) * G1 + g * H1 + u01]);
                float wl, wh; upk(wv, wl, wh);
                wp[0][g] = pk2(wl, wl); wp[1][g] = pk2(wh, wh);
            }
            #pragma unroll
            for (int p = 0; p < 8; p++) {
                u64t hv = lds64(&sH1w[k * HS1 + 2 * p]);
                #pragma unroll
                for (int g = 0; g < 4; g++) {
                    a1[0][g][p] = fma2(wp[0][g], hv, a1[0][g][p]);
                    a1[1][g][p] = fma2(wp[1][g], hv, a1[1][g][p]);
                }
            }
        }
        __syncwarp();                          // all reads of old h1 done (WAR)

        // pointwise layer1 + write new h1 (warp slab)
        #pragma unroll
        for (int u = 0; u < 2; u++) {
            #pragma unroll
            for (int p = 0; p < 8; p++) {
                float gi[2], gf[2], gg[2], go[2], hh[2];
                upk(a1[u][0][p], gi[0], gi[1]);
                upk(a1[u][1][p], gf[0], gf[1]);
                upk(a1[u][2][p], gg[0], gg[1]);
                upk(a1[u][3][p], go[0], go[1]);
                #pragma unroll
                for (int s = 0; s < 2; s++) {
                    float ii = sigf(gi[s]);
                    float ff = sigf(gf[s]);
                    float g_ = tanhf_(gg[s]);
                    float oo = sigf(go[s]);
                    float cc = ff * c1[u][2 * p + s] + ii * g_;
                    c1[u][2 * p + s] = cc;
                    hh[s] = oo * tanhf_(cc);
                }
                sts64(&sH1w[(u01 + u) * HS1 + 2 * p], pk2(hh[0], hh[1]));
            }
        }
        __syncwarp();                          // new h1 visible (RAW)

        // ================= layer 2 gates =================
        u64t a2[2][4][4];
        #pragma unroll
        for (int g = 0; g < 4; g++) {
            float blo = sB2[g * H2 + u02];
            float bhi = sB2[g * H2 + u02 + 1];
            u64t plo = pk2(blo, blo), phi = pk2(bhi, bhi);
            #pragma unroll
            for (int p = 0; p < 4; p++) { a2[0][g][p] = plo; a2[1][g][p] = phi; }
        }
        #pragma unroll 2
        for (int k = 0; k < H1; k++) {         // input = new h1
            u64t wp[2][4];
            #pragma unroll
            for (int g = 0; g < 4; g++) {
                u64t wv = lds64(&sW2T[k * G2 + g * H2 + u02]);
                float wl, wh; upk(wv, wl, wh);
                wp[0][g] = pk2(wl, wl); wp[1][g] = pk2(wh, wh);
            }
            #pragma unroll
            for (int p = 0; p < 4; p++) {
                u64t hv = lds64(&sH1w[k * HS1 + bh2 + 2 * p]);
                #pragma unroll
                for (int g = 0; g < 4; g++) {
                    a2[0][g][p] = fma2(wp[0][g], hv, a2[0][g][p]);
                    a2[1][g][p] = fma2(wp[1][g], hv, a2[1][g][p]);
                }
            }
        }
        #pragma unroll 2
        for (int k = 0; k < H2; k++) {         // recurrent = old h2
            u64t wp[2][4];
            #pragma unroll
            for (int g = 0; g < 4; g++) {
                u64t wv = lds64(&sW2T[(H1 + k) * G2 + g * H2 + u02]);
                float wl, wh; upk(wv, wl, wh);
                wp[0][g] = pk2(wl, wl); wp[1][g] = pk2(wh, wh);
            }
            #pragma unroll
            for (int p = 0; p < 4; p++) {
                u64t hv = lds64(&sH2w[k * HS2 + bh2 + 2 * p]);
                #pragma unroll
                for (int g = 0; g < 4; g++) {
                    a2[0][g][p] = fma2(wp[0][g], hv, a2[0][g][p]);
                    a2[1][g][p] = fma2(wp[1][g], hv, a2[1][g][p]);
                }
            }
        }
        __syncwarp();                          // all reads of old h2 done (WAR)

        // pointwise layer2 + write new h2
        #pragma unroll
        for (int u = 0; u < 2; u++) {
            #pragma unroll
            for (int p = 0; p < 4; p++) {
                float gi[2], gf[2], gg[2], go[2], hh[2];
                upk(a2[u][0][p], gi[0], gi[1]);
                upk(a2[u][1][p], gf[0], gf[1]);
                upk(a2[u][2][p], gg[0], gg[1]);
                upk(a2[u][3][p], go[0], go[1]);
                #pragma unroll
                for (int s = 0; s < 2; s++) {
                    float ii = sigf(gi[s]);
                    float ff = sigf(gf[s]);
                    float g_ = tanhf_(gg[s]);
                    float oo = sigf(go[s]);
                    float cc = ff * c2[u][2 * p + s] + ii * g_;
                    c2[u][2 * p + s] = cc;
                    hh[s] = oo * tanhf_(cc);
                }
                sts64(&sH2w[(u02 + u) * HS2 + bh2 + 2 * p], pk2(hh[0], hh[1]));
            }
        }
        __syncwarp();                          // new h2 visible for next step
    }

    // ================= head (warp-local): dense(16)+relu -> dot(16)+sigmoid ====
    if (lane < 16) {
        const int b = lane;
        float hv[H2];
        #pragma unroll
        for (int k = 0; k < H2; k++) hv[k] = sH2w[k * HS2 + b];
        float o = __ldg(&bo[0]);
        #pragma unroll
        for (int j = 0; j < 16; j++) {
            float s = __ldg(&bd[j]);
            #pragma unroll
            for (int k = 0; k < H2; k++) s += hv[k] * __ldg(&Wd[j * H2 + k]);
            o += fmaxf(s, 0.0f) * __ldg(&Wo[j]);
        }
        out[bbase + wid * 16 + b] = sigf(o);
    }
}

extern "C" void kernel_launch(void* const* d_in, const int* in_sizes, int n_in,
                              void* d_out, int out_size) {
    const float* x    = (const float*)d_in[0];
    const float* Wih1 = (const float*)d_in[1];
    const float* Whh1 = (const float*)d_in[2];
    const float* bih1 = (const float*)d_in[3];
    const float* bhh1 = (const float*)d_in[4];
    const float* Wih2 = (const float*)d_in[5];
    const float* Whh2 = (const float*)d_in[6];
    const float* bih2 = (const float*)d_in[7];
    const float* bhh2 = (const float*)d_in[8];
    const float* Wd   = (const float*)d_in[9];
    const float* bd   = (const float*)d_in[10];
    const float* Wo   = (const float*)d_in[11];
    const float* bo   = (const float*)d_in[12];
    float* out = (float*)d_out;

    static bool attr_set = false;
    if (!attr_set) {
        cudaFuncSetAttribute(momentum_lstm_kernel,
                             cudaFuncAttributeMaxDynamicSharedMemorySize, SMEM_BYTES);
        attr_set = true;
    }

    momentum_lstm_kernel<<<BATCH / BT, NT, SMEM_BYTES>>>(
        x, Wih1, Whh1, bih1, bhh1, Wih2, Whh2, bih2, bhh2, Wd, bd, Wo, bo, out);
}

// round 5
// speedup vs baseline: 1.5693x; 1.0388x over previous
#include <cuda_runtime.h>
#include <cuda_bf16.h>

// MomentumLSTM v5: persistent grid=152, 384 threads (12 warps = 3/SMSP),
// warp-task = 8 batches, 4096 tasks interleaved across warps for per-SMSP balance.
// Warp-local recurrence (no __syncthreads in loop). f32x2 batch-paired FMAs.

#define BATCH  32768
#define TT     60
#define DD     7
#define H1     64
#define G1     256
#define H2     32
#define G2     128
#define NT     384
#define NWARP  12
#define GRID   152
#define TB     8                 // batches per warp-task
#define NTASKS (BATCH / TB)      // 4096
#define WSLOTS (GRID * NWARP)    // 1824
#define HS1    10                // even stride: [64][10] per-warp h1 slab
#define HS2    10                // [32][10]
#define XS     8                 // [7][8]

// SMEM float offsets
#define OFF_W1T 0                // [71][256] rows 0..6 x-w, 7..70 h-w
#define OFF_W2T 18176            // [96][128]
#define OFF_B1  30464            // [256]
#define OFF_B2  30720            // [128]
#define OFF_H1  30848            // 12 x 640
#define OFF_H2  38528            // 12 x 320
#define OFF_X   42368            // 12 x 64 (7*8 padded to 64)
#define SMEM_FLOATS 43136
#define SMEM_BYTES  (SMEM_FLOATS * 4)   // 172544

typedef unsigned long long u64t;

__device__ __forceinline__ u64t pk2(float a, float b) {
    u64t r; asm("mov.b64 %0, {%1, %2};" : "=l"(r) : "f"(a), "f"(b)); return r;
}
__device__ __forceinline__ void upk(u64t v, float& lo, float& hi) {
    asm("mov.b64 {%0, %1}, %2;" : "=f"(lo), "=f"(hi) : "l"(v));
}
__device__ __forceinline__ u64t fma2(u64t a, u64t b, u64t c) {
    u64t d; asm("fma.rn.f32x2 %0, %1, %2, %3;" : "=l"(d) : "l"(a), "l"(b), "l"(c)); return d;
}
__device__ __forceinline__ u64t lds64(const float* p) {
    return *reinterpret_cast<const u64t*>(p);
}
__device__ __forceinline__ void sts64(float* p, u64t v) {
    *reinterpret_cast<u64t*>(p) = v;
}
__device__ __forceinline__ float sigf(float x) {
    return __fdividef(1.0f, 1.0f + __expf(-x));
}
__device__ __forceinline__ float tanhf_(float x) {
    return __fdividef(2.0f, 1.0f + __expf(-2.0f * x)) - 1.0f;
}

__global__ void __launch_bounds__(NT, 1)
momentum_lstm_kernel(const float* __restrict__ x,
                     const float* __restrict__ Wih1, const float* __restrict__ Whh1,
                     const float* __restrict__ bih1, const float* __restrict__ bhh1,
                     const float* __restrict__ Wih2, const float* __restrict__ Whh2,
                     const float* __restrict__ bih2, const float* __restrict__ bhh2,
                     const float* __restrict__ Wd,  const float* __restrict__ bd,
                     const float* __restrict__ Wo,  const float* __restrict__ bo,
                     float* __restrict__ out)
{
    extern __shared__ float sm[];
    float* sW1T = sm + OFF_W1T;
    float* sW2T = sm + OFF_W2T;
    float* sB1  = sm + OFF_B1;
    float* sB2  = sm + OFF_B2;

    const int tid  = threadIdx.x;
    const int lane = tid & 31;
    const int wid  = tid >> 5;

    float* sH1w = sm + OFF_H1 + wid * (H1 * HS1);
    float* sH2w = sm + OFF_H2 + wid * (H2 * HS2);
    float* sXw  = sm + OFF_X  + wid * 64;

    // ---------------- cooperative weight staging (only global sync) ----------------
    for (int i = tid; i < DD * G1; i += NT) {
        int d = i >> 8, g = i & 255;
        sW1T[d * G1 + g] = Wih1[g * DD + d];
    }
    for (int i = tid; i < H1 * G1; i += NT) {
        int k = i >> 8, g = i & 255;
        sW1T[(DD + k) * G1 + g] = Whh1[g * H1 + k];
    }
    for (int i = tid; i < (H1 + H2) * G2; i += NT) {
        int k = i >> 7, g = i & 127;
        sW2T[i] = (k < H1) ? Wih2[g * H1 + k] : Whh2[g * H2 + (k - H1)];
    }
    if (tid < G1) sB1[tid] = bih1[tid] + bhh1[tid];
    if (tid < G2) sB2[tid] = bih2[tid] + bhh2[tid];
    __syncthreads();

    // ---------------- warp-local tilings ----------------
    const int u01 = 2 * lane;               // layer1: lanes span 64 units
    const int u02 = 2 * (lane & 15);        // layer2: 16 lanes span 32 units
    const int bh2 = (lane >> 4) * 4;        // layer2: half-warp batch split (4 each)

    const u64t bia1_0 = lds64(&sB1[0 * H1 + u01]);
    const u64t bia1_1 = lds64(&sB1[1 * H1 + u01]);
    const u64t bia1_2 = lds64(&sB1[2 * H1 + u01]);
    const u64t bia1_3 = lds64(&sB1[3 * H1 + u01]);
    const u64t bia2_0 = lds64(&sB2[0 * H2 + u02]);
    const u64t bia2_1 = lds64(&sB2[1 * H2 + u02]);
    const u64t bia2_2 = lds64(&sB2[2 * H2 + u02]);
    const u64t bia2_3 = lds64(&sB2[3 * H2 + u02]);

    const int gw = wid * GRID + blockIdx.x;   // interleaved: mixes 2- and 3-task warps per SM

    for (int tau = gw; tau < NTASKS; tau += WSLOTS) {
        const float* xg = x + (size_t)tau * TB * (TT * DD);

        // zero warp-local state
        for (int i = lane; i < H1 * HS1; i += 32) sH1w[i] = 0.0f;
        for (int i = lane; i < H2 * HS2; i += 32) sH2w[i] = 0.0f;
        __syncwarp();

        float c1[2][TB];
        #pragma unroll
        for (int u = 0; u < 2; u++)
            #pragma unroll
            for (int b = 0; b < TB; b++) c1[u][b] = 0.0f;
        float c2[2][4];
        #pragma unroll
        for (int u = 0; u < 2; u++)
            #pragma unroll
            for (int b = 0; b < 4; b++) c2[u][b] = 0.0f;

        // prefetch x(t=0): 8 batches x 7 dims = 56 floats
        float xr[2];
        #pragma unroll
        for (int j = 0; j < 2; j++) {
            int idx = 32 * j + lane;
            if (idx < DD * TB) {
                int b = idx / DD, d = idx - b * DD;
                xr[j] = xg[b * (TT * DD) + d];
            }
        }

        for (int t = 0; t < TT; t++) {
            // store x(t) into warp slab; prefetch x(t+1)
            #pragma unroll
            for (int j = 0; j < 2; j++) {
                int idx = 32 * j + lane;
                if (idx < DD * TB) {
                    int b = idx / DD, d = idx - b * DD;
                    sXw[d * XS + b] = xr[j];
                }
            }
            __syncwarp();
            if (t + 1 < TT) {
                #pragma unroll
                for (int j = 0; j < 2; j++) {
                    int idx = 32 * j + lane;
                    if (idx < DD * TB) {
                        int b = idx / DD, d = idx - b * DD;
                        xr[j] = xg[b * (TT * DD) + (t + 1) * DD + d];
                    }
                }
            }

            // ================= layer 1 gates =================
            u64t a1[2][4][4];
            #pragma unroll
            for (int p = 0; p < 4; p++) {
                a1[0][0][p] = bia1_0; a1[0][1][p] = bia1_1;
                a1[0][2][p] = bia1_2; a1[0][3][p] = bia1_3;
            }
            // high-unit copies (bias pair for u01+1 is the hi half trick not valid:
            // a1[1] accumulates gates for unit u01+1 duplicated scalar weights,
            // bias differs per unit -> build from scalar
            #pragma unroll
            for (int g = 0; g < 4; g++) {
                float blo, bhi;
                upk(g == 0 ? bia1_0 : g == 1 ? bia1_1 : g == 2 ? bia1_2 : bia1_3, blo, bhi);
                u64t plo = pk2(blo, blo), phi = pk2(bhi, bhi);
                #pragma unroll
                for (int p = 0; p < 4; p++) { a1[0][g][p] = plo; a1[1][g][p] = phi; }
            }
            #pragma unroll
            for (int d = 0; d < DD; d++) {
                u64t wp[2][4];
                #pragma unroll
                for (int g = 0; g < 4; g++) {
                    u64t wv = lds64(&sW1T[d * G1 + g * H1 + u01]);
                    float wl, wh; upk(wv, wl, wh);
                    wp[0][g] = pk2(wl, wl); wp[1][g] = pk2(wh, wh);
                }
                #pragma unroll
                for (int p = 0; p < 4; p++) {
                    u64t xv = lds64(&sXw[d * XS + 2 * p]);
                    #pragma unroll
                    for (int g = 0; g < 4; g++) {
                        a1[0][g][p] = fma2(wp[0][g], xv, a1[0][g][p]);
                        a1[1][g][p] = fma2(wp[1][g], xv, a1[1][g][p]);
                    }
                }
            }
            #pragma unroll 2
            for (int k = 0; k < H1; k++) {
                u64t wp[2][4];
                #pragma unroll
                for (int g = 0; g < 4; g++) {
                    u64t wv = lds64(&sW1T[(DD + k) * G1 + g * H1 + u01]);
                    float wl, wh; upk(wv, wl, wh);
                    wp[0][g] = pk2(wl, wl); wp[1][g] = pk2(wh, wh);
                }
                #pragma unroll
                for (int p = 0; p < 4; p++) {
                    u64t hv = lds64(&sH1w[k * HS1 + 2 * p]);
                    #pragma unroll
                    for (int g = 0; g < 4; g++) {
                        a1[0][g][p] = fma2(wp[0][g], hv, a1[0][g][p]);
                        a1[1][g][p] = fma2(wp[1][g], hv, a1[1][g][p]);
                    }
                }
            }
            __syncwarp();                      // WAR on old h1

            // pointwise layer1 + write new h1
            #pragma unroll
            for (int u = 0; u < 2; u++) {
                #pragma unroll
                for (int p = 0; p < 4; p++) {
                    float gi[2], gf[2], gg[2], go[2], hh[2];
                    upk(a1[u][0][p], gi[0], gi[1]);
                    upk(a1[u][1][p], gf[0], gf[1]);
                    upk(a1[u][2][p], gg[0], gg[1]);
                    upk(a1[u][3][p], go[0], go[1]);
                    #pragma unroll
                    for (int s = 0; s < 2; s++) {
                        float ii = sigf(gi[s]);
                        float ff = sigf(gf[s]);
                        float g_ = tanhf_(gg[s]);
                        float oo = sigf(go[s]);
                        float cc = ff * c1[u][2 * p + s] + ii * g_;
                        c1[u][2 * p + s] = cc;
                        hh[s] = oo * tanhf_(cc);
                    }
                    sts64(&sH1w[(u01 + u) * HS1 + 2 * p], pk2(hh[0], hh[1]));
                }
            }
            __syncwarp();                      // RAW: new h1 visible

            // ================= layer 2 gates =================
            u64t a2[2][4][2];
            #pragma unroll
            for (int g = 0; g < 4; g++) {
                float blo, bhi;
                upk(g == 0 ? bia2_0 : g == 1 ? bia2_1 : g == 2 ? bia2_2 : bia2_3, blo, bhi);
                u64t plo = pk2(blo, blo), phi = pk2(bhi, bhi);
                #pragma unroll
                for (int p = 0; p < 2; p++) { a2[0][g][p] = plo; a2[1][g][p] = phi; }
            }
            #pragma unroll 2
            for (int k = 0; k < H1; k++) {     // input = new h1
                u64t wp[2][4];
                #pragma unroll
                for (int g = 0; g < 4; g++) {
                    u64t wv = lds64(&sW2T[k * G2 + g * H2 + u02]);
                    float wl, wh; upk(wv, wl, wh);
                    wp[0][g] = pk2(wl, wl); wp[1][g] = pk2(wh, wh);
                }
                #pragma unroll
                for (int p = 0; p < 2; p++) {
                    u64t hv = lds64(&sH1w[k * HS1 + bh2 + 2 * p]);
                    #pragma unroll
                    for (int g = 0; g < 4; g++) {
                        a2[0][g][p] = fma2(wp[0][g], hv, a2[0][g][p]);
                        a2[1][g][p] = fma2(wp[1][g], hv, a2[1][g][p]);
                    }
                }
            }
            #pragma unroll 2
            for (int k = 0; k < H2; k++) {     // recurrent = old h2
                u64t wp[2][4];
                #pragma unroll
                for (int g = 0; g < 4; g++) {
                    u64t wv = lds64(&sW2T[(H1 + k) * G2 + g * H2 + u02]);
                    float wl, wh; upk(wv, wl, wh);
                    wp[0][g] = pk2(wl, wl); wp[1][g] = pk2(wh, wh);
                }
                #pragma unroll
                for (int p = 0; p < 2; p++) {
                    u64t hv = lds64(&sH2w[k * HS2 + bh2 + 2 * p]);
                    #pragma unroll
                    for (int g = 0; g < 4; g++) {
                        a2[0][g][p] = fma2(wp[0][g], hv, a2[0][g][p]);
                        a2[1][g][p] = fma2(wp[1][g], hv, a2[1][g][p]);
                    }
                }
            }
            __syncwarp();                      // WAR on old h2

            // pointwise layer2 + write new h2
            #pragma unroll
            for (int u = 0; u < 2; u++) {
                #pragma unroll
                for (int p = 0; p < 2; p++) {
                    float gi[2], gf[2], gg[2], go[2], hh[2];
                    upk(a2[u][0][p], gi[0], gi[1]);
                    upk(a2[u][1][p], gf[0], gf[1]);
                    upk(a2[u][2][p], gg[0], gg[1]);
                    upk(a2[u][3][p], go[0], go[1]);
                    #pragma unroll
                    for (int s = 0; s < 2; s++) {
                        float ii = sigf(gi[s]);
                        float ff = sigf(gf[s]);
                        float g_ = tanhf_(gg[s]);
                        float oo = sigf(go[s]);
                        float cc = ff * c2[u][2 * p + s] + ii * g_;
                        c2[u][2 * p + s] = cc;
                        hh[s] = oo * tanhf_(cc);
                    }
                    sts64(&sH2w[(u02 + u) * HS2 + bh2 + 2 * p], pk2(hh[0], hh[1]));
                }
            }
            __syncwarp();                      // new h2 visible
        }

        // ================= head: dense(16)+relu -> dot(16)+sigmoid =============
        if (lane < TB) {
            const int b = lane;
            float hv[H2];
            #pragma unroll
            for (int k = 0; k < H2; k++) hv[k] = sH2w[k * HS2 + b];
            float o = __ldg(&bo[0]);
            #pragma unroll
            for (int j = 0; j < 16; j++) {
                float s = __ldg(&bd[j]);
                #pragma unroll
                for (int k = 0; k < H2; k++) s += hv[k] * __ldg(&Wd[j * H2 + k]);
                o += fmaxf(s, 0.0f) * __ldg(&Wo[j]);
            }
            out[tau * TB + b] = sigf(o);
        }
        __syncwarp();                          // head reads done before next-task zeroing
    }
}

extern "C" void kernel_launch(void* const* d_in, const int* in_sizes, int n_in,
                              void* d_out, int out_size) {
    const float* x    = (const float*)d_in[0];
    const float* Wih1 = (const float*)d_in[1];
    const float* Whh1 = (const float*)d_in[2];
    const float* bih1 = (const float*)d_in[3];
    const float* bhh1 = (const float*)d_in[4];
    const float* Wih2 = (const float*)d_in[5];
    const float* Whh2 = (const float*)d_in[6];
    const float* bih2 = (const float*)d_in[7];
    const float* bhh2 = (const float*)d_in[8];
    const float* Wd   = (const float*)d_in[9];
    const float* bd   = (const float*)d_in[10];
    const float* Wo   = (const float*)d_in[11];
    const float* bo   = (const float*)d_in[12];
    float* out = (float*)d_out;

    static bool attr_set = false;
    if (!attr_set) {
        cudaFuncSetAttribute(momentum_lstm_kernel,
                             cudaFuncAttributeMaxDynamicSharedMemorySize, SMEM_BYTES);
        attr_set = true;
    }

    momentum_lstm_kernel<<<GRID, NT, SMEM_BYTES>>>(
        x, Wih1, Whh1, bih1, bhh1, Wih2, Whh2, bih2, bhh2, Wd, bd, Wo, bo, out);
}

// round 6
// speedup vs baseline: 1.6662x; 1.0617x over previous
#include <cuda_runtime.h>
#include <cuda_bf16.h>

// MomentumLSTM v6: v5 (persistent 152x384, warp-local recurrence, f32x2 FMAs)
// + HW tanh (MUFU.TANH) activations: tanh = 1 issue, sigmoid = 0.5*tanh(0.5x)+0.5.
// Removes the exp/rcp chains that made the kernel issue-bound. Head sigmoid stays exact.

#define BATCH  32768
#define TT     60
#define DD     7
#define H1     64
#define G1     256
#define H2     32
#define G2     128
#define NT     384
#define NWARP  12
#define GRID   152
#define TB     8                 // batches per warp-task
#define NTASKS (BATCH / TB)      // 4096
#define WSLOTS (GRID * NWARP)    // 1824
#define HS1    10                // even stride: [64][10] per-warp h1 slab
#define HS2    10                // [32][10]
#define XS     8                 // [7][8]

// SMEM float offsets
#define OFF_W1T 0                // [71][256] rows 0..6 x-w, 7..70 h-w
#define OFF_W2T 18176            // [96][128]
#define OFF_B1  30464            // [256]
#define OFF_B2  30720            // [128]
#define OFF_H1  30848            // 12 x 640
#define OFF_H2  38528            // 12 x 320
#define OFF_X   42368            // 12 x 64
#define SMEM_FLOATS 43136
#define SMEM_BYTES  (SMEM_FLOATS * 4)   // 172544

typedef unsigned long long u64t;

__device__ __forceinline__ u64t pk2(float a, float b) {
    u64t r; asm("mov.b64 %0, {%1, %2};" : "=l"(r) : "f"(a), "f"(b)); return r;
}
__device__ __forceinline__ void upk(u64t v, float& lo, float& hi) {
    asm("mov.b64 {%0, %1}, %2;" : "=f"(lo), "=f"(hi) : "l"(v));
}
__device__ __forceinline__ u64t fma2(u64t a, u64t b, u64t c) {
    u64t d; asm("fma.rn.f32x2 %0, %1, %2, %3;" : "=l"(d) : "l"(a), "l"(b), "l"(c)); return d;
}
__device__ __forceinline__ u64t lds64(const float* p) {
    return *reinterpret_cast<const u64t*>(p);
}
__device__ __forceinline__ void sts64(float* p, u64t v) {
    *reinterpret_cast<u64t*>(p) = v;
}
// HW tanh (MUFU.TANH): 1 issue
__device__ __forceinline__ float tanha(float x) {
    float y; asm("tanh.approx.f32 %0, %1;" : "=f"(y) : "f"(x)); return y;
}
// sigmoid via HW tanh: 3 issues (FMUL, MUFU, FFMA)
__device__ __forceinline__ float siga(float x) {
    return fmaf(0.5f, tanha(0.5f * x), 0.5f);
}
// exact sigmoid for the final output only
__device__ __forceinline__ float sigx(float x) {
    return __fdividef(1.0f, 1.0f + __expf(-x));
}

__global__ void __launch_bounds__(NT, 1)
momentum_lstm_kernel(const float* __restrict__ x,
                     const float* __restrict__ Wih1, const float* __restrict__ Whh1,
                     const float* __restrict__ bih1, const float* __restrict__ bhh1,
                     const float* __restrict__ Wih2, const float* __restrict__ Whh2,
                     const float* __restrict__ bih2, const float* __restrict__ bhh2,
                     const float* __restrict__ Wd,  const float* __restrict__ bd,
                     const float* __restrict__ Wo,  const float* __restrict__ bo,
                     float* __restrict__ out)
{
    extern __shared__ float sm[];
    float* sW1T = sm + OFF_W1T;
    float* sW2T = sm + OFF_W2T;
    float* sB1  = sm + OFF_B1;
    float* sB2  = sm + OFF_B2;

    const int tid  = threadIdx.x;
    const int lane = tid & 31;
    const int wid  = tid >> 5;

    float* sH1w = sm + OFF_H1 + wid * (H1 * HS1);
    float* sH2w = sm + OFF_H2 + wid * (H2 * HS2);
    float* sXw  = sm + OFF_X  + wid * 64;

    // ---------------- cooperative weight staging (only global sync) ----------------
    for (int i = tid; i < DD * G1; i += NT) {
        int d = i >> 8, g = i & 255;
        sW1T[d * G1 + g] = Wih1[g * DD + d];
    }
    for (int i = tid; i < H1 * G1; i += NT) {
        int k = i >> 8, g = i & 255;
        sW1T[(DD + k) * G1 + g] = Whh1[g * H1 + k];
    }
    for (int i = tid; i < (H1 + H2) * G2; i += NT) {
        int k = i >> 7, g = i & 127;
        sW2T[i] = (k < H1) ? Wih2[g * H1 + k] : Whh2[g * H2 + (k - H1)];
    }
    if (tid < G1) sB1[tid] = bih1[tid] + bhh1[tid];
    if (tid < G2) sB2[tid] = bih2[tid] + bhh2[tid];
    __syncthreads();

    // ---------------- warp-local tilings ----------------
    const int u01 = 2 * lane;               // layer1: lanes span 64 units
    const int u02 = 2 * (lane & 15);        // layer2: 16 lanes span 32 units
    const int bh2 = (lane >> 4) * 4;        // layer2: half-warp batch split (4 each)

    const u64t bia1_0 = lds64(&sB1[0 * H1 + u01]);
    const u64t bia1_1 = lds64(&sB1[1 * H1 + u01]);
    const u64t bia1_2 = lds64(&sB1[2 * H1 + u01]);
    const u64t bia1_3 = lds64(&sB1[3 * H1 + u01]);
    const u64t bia2_0 = lds64(&sB2[0 * H2 + u02]);
    const u64t bia2_1 = lds64(&sB2[1 * H2 + u02]);
    const u64t bia2_2 = lds64(&sB2[2 * H2 + u02]);
    const u64t bia2_3 = lds64(&sB2[3 * H2 + u02]);

    const int gw = wid * GRID + blockIdx.x;   // interleaved task id

    for (int tau = gw; tau < NTASKS; tau += WSLOTS) {
        const float* xg = x + (size_t)tau * TB * (TT * DD);

        for (int i = lane; i < H1 * HS1; i += 32) sH1w[i] = 0.0f;
        for (int i = lane; i < H2 * HS2; i += 32) sH2w[i] = 0.0f;
        __syncwarp();

        float c1[2][TB];
        #pragma unroll
        for (int u = 0; u < 2; u++)
            #pragma unroll
            for (int b = 0; b < TB; b++) c1[u][b] = 0.0f;
        float c2[2][4];
        #pragma unroll
        for (int u = 0; u < 2; u++)
            #pragma unroll
            for (int b = 0; b < 4; b++) c2[u][b] = 0.0f;

        // prefetch x(t=0)
        float xr[2];
        #pragma unroll
        for (int j = 0; j < 2; j++) {
            int idx = 32 * j + lane;
            if (idx < DD * TB) {
                int b = idx / DD, d = idx - b * DD;
                xr[j] = xg[b * (TT * DD) + d];
            }
        }

        for (int t = 0; t < TT; t++) {
            // store x(t); prefetch x(t+1)
            #pragma unroll
            for (int j = 0; j < 2; j++) {
                int idx = 32 * j + lane;
                if (idx < DD * TB) {
                    int b = idx / DD, d = idx - b * DD;
                    sXw[d * XS + b] = xr[j];
                }
            }
            __syncwarp();
            if (t + 1 < TT) {
                #pragma unroll
                for (int j = 0; j < 2; j++) {
                    int idx = 32 * j + lane;
                    if (idx < DD * TB) {
                        int b = idx / DD, d = idx - b * DD;
                        xr[j] = xg[b * (TT * DD) + (t + 1) * DD + d];
                    }
                }
            }

            // ================= layer 1 gates =================
            u64t a1[2][4][4];
            #pragma unroll
            for (int g = 0; g < 4; g++) {
                float blo, bhi;
                upk(g == 0 ? bia1_0 : g == 1 ? bia1_1 : g == 2 ? bia1_2 : bia1_3, blo, bhi);
                u64t plo = pk2(blo, blo), phi = pk2(bhi, bhi);
                #pragma unroll
                for (int p = 0; p < 4; p++) { a1[0][g][p] = plo; a1[1][g][p] = phi; }
            }
            #pragma unroll
            for (int d = 0; d < DD; d++) {
                u64t wp[2][4];
                #pragma unroll
                for (int g = 0; g < 4; g++) {
                    u64t wv = lds64(&sW1T[d * G1 + g * H1 + u01]);
                    float wl, wh; upk(wv, wl, wh);
                    wp[0][g] = pk2(wl, wl); wp[1][g] = pk2(wh, wh);
                }
                #pragma unroll
                for (int p = 0; p < 4; p++) {
                    u64t xv = lds64(&sXw[d * XS + 2 * p]);
                    #pragma unroll
                    for (int g = 0; g < 4; g++) {
                        a1[0][g][p] = fma2(wp[0][g], xv, a1[0][g][p]);
                        a1[1][g][p] = fma2(wp[1][g], xv, a1[1][g][p]);
                    }
                }
            }
            #pragma unroll 2
            for (int k = 0; k < H1; k++) {
                u64t wp[2][4];
                #pragma unroll
                for (int g = 0; g < 4; g++) {
                    u64t wv = lds64(&sW1T[(DD + k) * G1 + g * H1 + u01]);
                    float wl, wh; upk(wv, wl, wh);
                    wp[0][g] = pk2(wl, wl); wp[1][g] = pk2(wh, wh);
                }
                #pragma unroll
                for (int p = 0; p < 4; p++) {
                    u64t hv = lds64(&sH1w[k * HS1 + 2 * p]);
                    #pragma unroll
                    for (int g = 0; g < 4; g++) {
                        a1[0][g][p] = fma2(wp[0][g], hv, a1[0][g][p]);
                        a1[1][g][p] = fma2(wp[1][g], hv, a1[1][g][p]);
                    }
                }
            }
            __syncwarp();                      // WAR on old h1

            // pointwise layer1 + write new h1 (HW tanh activations)
            #pragma unroll
            for (int u = 0; u < 2; u++) {
                #pragma unroll
                for (int p = 0; p < 4; p++) {
                    float gi[2], gf[2], gg[2], go[2], hh[2];
                    upk(a1[u][0][p], gi[0], gi[1]);
                    upk(a1[u][1][p], gf[0], gf[1]);
                    upk(a1[u][2][p], gg[0], gg[1]);
                    upk(a1[u][3][p], go[0], go[1]);
                    #pragma unroll
                    for (int s = 0; s < 2; s++) {
                        float ii = siga(gi[s]);
                        float ff = siga(gf[s]);
                        float g_ = tanha(gg[s]);
                        float oo = siga(go[s]);
                        float cc = ff * c1[u][2 * p + s] + ii * g_;
                        c1[u][2 * p + s] = cc;
                        hh[s] = oo * tanha(cc);
                    }
                    sts64(&sH1w[(u01 + u) * HS1 + 2 * p], pk2(hh[0], hh[1]));
                }
            }
            __syncwarp();                      // RAW: new h1 visible

            // ================= layer 2 gates =================
            u64t a2[2][4][2];
            #pragma unroll
            for (int g = 0; g < 4; g++) {
                float blo, bhi;
                upk(g == 0 ? bia2_0 : g == 1 ? bia2_1 : g == 2 ? bia2_2 : bia2_3, blo, bhi);
                u64t plo = pk2(blo, blo), phi = pk2(bhi, bhi);
                #pragma unroll
                for (int p = 0; p < 2; p++) { a2[0][g][p] = plo; a2[1][g][p] = phi; }
            }
            #pragma unroll 2
            for (int k = 0; k < H1; k++) {     // input = new h1
                u64t wp[2][4];
                #pragma unroll
                for (int g = 0; g < 4; g++) {
                    u64t wv = lds64(&sW2T[k * G2 + g * H2 + u02]);
                    float wl, wh; upk(wv, wl, wh);
                    wp[0][g] = pk2(wl, wl); wp[1][g] = pk2(wh, wh);
                }
                #pragma unroll
                for (int p = 0; p < 2; p++) {
                    u64t hv = lds64(&sH1w[k * HS1 + bh2 + 2 * p]);
                    #pragma unroll
                    for (int g = 0; g < 4; g++) {
                        a2[0][g][p] = fma2(wp[0][g], hv, a2[0][g][p]);
                        a2[1][g][p] = fma2(wp[1][g], hv, a2[1][g][p]);
                    }
                }
            }
            #pragma unroll 2
            for (int k = 0; k < H2; k++) {     // recurrent = old h2
                u64t wp[2][4];
                #pragma unroll
                for (int g = 0; g < 4; g++) {
                    u64t wv = lds64(&sW2T[(H1 + k) * G2 + g * H2 + u02]);
                    float wl, wh; upk(wv, wl, wh);
                    wp[0][g] = pk2(wl, wl); wp[1][g] = pk2(wh, wh);
                }
                #pragma unroll
                for (int p = 0; p < 2; p++) {
                    u64t hv = lds64(&sH2w[k * HS2 + bh2 + 2 * p]);
                    #pragma unroll
                    for (int g = 0; g < 4; g++) {
                        a2[0][g][p] = fma2(wp[0][g], hv, a2[0][g][p]);
                        a2[1][g][p] = fma2(wp[1][g], hv, a2[1][g][p]);
                    }
                }
            }
            __syncwarp();                      // WAR on old h2

            // pointwise layer2 + write new h2
            #pragma unroll
            for (int u = 0; u < 2; u++) {
                #pragma unroll
                for (int p = 0; p < 2; p++) {
                    float gi[2], gf[2], gg[2], go[2], hh[2];
                    upk(a2[u][0][p], gi[0], gi[1]);
                    upk(a2[u][1][p], gf[0], gf[1]);
                    upk(a2[u][2][p], gg[0], gg[1]);
                    upk(a2[u][3][p], go[0], go[1]);
                    #pragma unroll
                    for (int s = 0; s < 2; s++) {
                        float ii = siga(gi[s]);
                        float ff = siga(gf[s]);
                        float g_ = tanha(gg[s]);
                        float oo = siga(go[s]);
                        float cc = ff * c2[u][2 * p + s] + ii * g_;
                        c2[u][2 * p + s] = cc;
                        hh[s] = oo * tanha(cc);
                    }
                    sts64(&sH2w[(u02 + u) * HS2 + bh2 + 2 * p], pk2(hh[0], hh[1]));
                }
            }
            __syncwarp();                      // new h2 visible
        }

        // ================= head: dense(16)+relu -> dot(16)+sigmoid =============
        if (lane < TB) {
            const int b = lane;
            float hv[H2];
            #pragma unroll
            for (int k = 0; k < H2; k++) hv[k] = sH2w[k * HS2 + b];
            float o = __ldg(&bo[0]);
            #pragma unroll
            for (int j = 0; j < 16; j++) {
                float s = __ldg(&bd[j]);
                #pragma unroll
                for (int k = 0; k < H2; k++) s += hv[k] * __ldg(&Wd[j * H2 + k]);
                o += fmaxf(s, 0.0f) * __ldg(&Wo[j]);
            }
            out[tau * TB + b] = sigx(o);       // exact sigmoid at output
        }
        __syncwarp();                          // head reads done before next-task zeroing
    }
}

extern "C" void kernel_launch(void* const* d_in, const int* in_sizes, int n_in,
                              void* d_out, int out_size) {
    const float* x    = (const float*)d_in[0];
    const float* Wih1 = (const float*)d_in[1];
    const float* Whh1 = (const float*)d_in[2];
    const float* bih1 = (const float*)d_in[3];
    const float* bhh1 = (const float*)d_in[4];
    const float* Wih2 = (const float*)d_in[5];
    const float* Whh2 = (const float*)d_in[6];
    const float* bih2 = (const float*)d_in[7];
    const float* bhh2 = (const float*)d_in[8];
    const float* Wd   = (const float*)d_in[9];
    const float* bd   = (const float*)d_in[10];
    const float* Wo   = (const float*)d_in[11];
    const float* bo   = (const float*)d_in[12];
    float* out = (float*)d_out;

    static bool attr_set = false;
    if (!attr_set) {
        cudaFuncSetAttribute(momentum_lstm_kernel,
                             cudaFuncAttributeMaxDynamicSharedMemorySize, SMEM_BYTES);
        attr_set = true;
    }

    momentum_lstm_kernel<<<GRID, NT, SMEM_BYTES>>>(
        x, Wih1, Whh1, bih1, bhh1, Wih2, Whh2, bih2, bhh2, Wd, bd, Wo, bo, out);
}

// round 7
// speedup vs baseline: 1.6671x; 1.0006x over previous
#include <cuda_runtime.h>
#include <cuda_bf16.h>

// MomentumLSTM v6: v5 (persistent 152x384, warp-local recurrence, f32x2 FMAs)
// + HW tanh (MUFU.TANH) activations: tanh = 1 issue, sigmoid = 0.5*tanh(0.5x)+0.5.
// Removes the exp/rcp chains that made the kernel issue-bound. Head sigmoid stays exact.

#define BATCH  32768
#define TT     60
#define DD     7
#define H1     64
#define G1     256
#define H2     32
#define G2     128
#define NT     384
#define NWARP  12
#define GRID   152
#define TB     8                 // batches per warp-task
#define NTASKS (BATCH / TB)      // 4096
#define WSLOTS (GRID * NWARP)    // 1824
#define HS1    10                // even stride: [64][10] per-warp h1 slab
#define HS2    10                // [32][10]
#define XS     8                 // [7][8]

// SMEM float offsets
#define OFF_W1T 0                // [71][256] rows 0..6 x-w, 7..70 h-w
#define OFF_W2T 18176            // [96][128]
#define OFF_B1  30464            // [256]
#define OFF_B2  30720            // [128]
#define OFF_H1  30848            // 12 x 640
#define OFF_H2  38528            // 12 x 320
#define OFF_X   42368            // 12 x 64
#define SMEM_FLOATS 43136
#define SMEM_BYTES  (SMEM_FLOATS * 4)   // 172544

typedef unsigned long long u64t;

__device__ __forceinline__ u64t pk2(float a, float b) {
    u64t r; asm("mov.b64 %0, {%1, %2};" : "=l"(r) : "f"(a), "f"(b)); return r;
}
__device__ __forceinline__ void upk(u64t v, float& lo, float& hi) {
    asm("mov.b64 {%0, %1}, %2;" : "=f"(lo), "=f"(hi) : "l"(v));
}
__device__ __forceinline__ u64t fma2(u64t a, u64t b, u64t c) {
    u64t d; asm("fma.rn.f32x2 %0, %1, %2, %3;" : "=l"(d) : "l"(a), "l"(b), "l"(c)); return d;
}
__device__ __forceinline__ u64t lds64(const float* p) {
    return *reinterpret_cast<const u64t*>(p);
}
__device__ __forceinline__ void sts64(float* p, u64t v) {
    *reinterpret_cast<u64t*>(p) = v;
}
// HW tanh (MUFU.TANH): 1 issue
__device__ __forceinline__ float tanha(float x) {
    float y; asm("tanh.approx.f32 %0, %1;" : "=f"(y) : "f"(x)); return y;
}
// sigmoid via HW tanh: 3 issues (FMUL, MUFU, FFMA)
__device__ __forceinline__ float siga(float x) {
    return fmaf(0.5f, tanha(0.5f * x), 0.5f);
}
// exact sigmoid for the final output only
__device__ __forceinline__ float sigx(float x) {
    return __fdividef(1.0f, 1.0f + __expf(-x));
}

__global__ void __launch_bounds__(NT, 1)
momentum_lstm_kernel(const float* __restrict__ x,
                     const float* __restrict__ Wih1, const float* __restrict__ Whh1,
                     const float* __restrict__ bih1, const float* __restrict__ bhh1,
                     const float* __restrict__ Wih2, const float* __restrict__ Whh2,
                     const float* __restrict__ bih2, const float* __restrict__ bhh2,
                     const float* __restrict__ Wd,  const float* __restrict__ bd,
                     const float* __restrict__ Wo,  const float* __restrict__ bo,
                     float* __restrict__ out)
{
    extern __shared__ float sm[];
    float* sW1T = sm + OFF_W1T;
    float* sW2T = sm + OFF_W2T;
    float* sB1  = sm + OFF_B1;
    float* sB2  = sm + OFF_B2;

    const int tid  = threadIdx.x;
    const int lane = tid & 31;
    const int wid  = tid >> 5;

    float* sH1w = sm + OFF_H1 + wid * (H1 * HS1);
    float* sH2w = sm + OFF_H2 + wid * (H2 * HS2);
    float* sXw  = sm + OFF_X  + wid * 64;

    // ---------------- cooperative weight staging (only global sync) ----------------
    for (int i = tid; i < DD * G1; i += NT) {
        int d = i >> 8, g = i & 255;
        sW1T[d * G1 + g] = Wih1[g * DD + d];
    }
    for (int i = tid; i < H1 * G1; i += NT) {
        int k = i >> 8, g = i & 255;
        sW1T[(DD + k) * G1 + g] = Whh1[g * H1 + k];
    }
    for (int i = tid; i < (H1 + H2) * G2; i += NT) {
        int k = i >> 7, g = i & 127;
        sW2T[i] = (k < H1) ? Wih2[g * H1 + k] : Whh2[g * H2 + (k - H1)];
    }
    if (tid < G1) sB1[tid] = bih1[tid] + bhh1[tid];
    if (tid < G2) sB2[tid] = bih2[tid] + bhh2[tid];
    __syncthreads();

    // ---------------- warp-local tilings ----------------
    const int u01 = 2 * lane;               // layer1: lanes span 64 units
    const int u02 = 2 * (lane & 15);        // layer2: 16 lanes span 32 units
    const int bh2 = (lane >> 4) * 4;        // layer2: half-warp batch split (4 each)

    const u64t bia1_0 = lds64(&sB1[0 * H1 + u01]);
    const u64t bia1_1 = lds64(&sB1[1 * H1 + u01]);
    const u64t bia1_2 = lds64(&sB1[2 * H1 + u01]);
    const u64t bia1_3 = lds64(&sB1[3 * H1 + u01]);
    const u64t bia2_0 = lds64(&sB2[0 * H2 + u02]);
    const u64t bia2_1 = lds64(&sB2[1 * H2 + u02]);
    const u64t bia2_2 = lds64(&sB2[2 * H2 + u02]);
    const u64t bia2_3 = lds64(&sB2[3 * H2 + u02]);

    const int gw = wid * GRID + blockIdx.x;   // interleaved task id

    for (int tau = gw; tau < NTASKS; tau += WSLOTS) {
        const float* xg = x + (size_t)tau * TB * (TT * DD);

        for (int i = lane; i < H1 * HS1; i += 32) sH1w[i] = 0.0f;
        for (int i = lane; i < H2 * HS2; i += 32) sH2w[i] = 0.0f;
        __syncwarp();

        float c1[2][TB];
        #pragma unroll
        for (int u = 0; u < 2; u++)
            #pragma unroll
            for (int b = 0; b < TB; b++) c1[u][b] = 0.0f;
        float c2[2][4];
        #pragma unroll
        for (int u = 0; u < 2; u++)
            #pragma unroll
            for (int b = 0; b < 4; b++) c2[u][b] = 0.0f;

        // prefetch x(t=0)
        float xr[2];
        #pragma unroll
        for (int j = 0; j < 2; j++) {
            int idx = 32 * j + lane;
            if (idx < DD * TB) {
                int b = idx / DD, d = idx - b * DD;
                xr[j] = xg[b * (TT * DD) + d];
            }
        }

        for (int t = 0; t < TT; t++) {
            // store x(t); prefetch x(t+1)
            #pragma unroll
            for (int j = 0; j < 2; j++) {
                int idx = 32 * j + lane;
                if (idx < DD * TB) {
                    int b = idx / DD, d = idx - b * DD;
                    sXw[d * XS + b] = xr[j];
                }
            }
            __syncwarp();
            if (t + 1 < TT) {
                #pragma unroll
                for (int j = 0; j < 2; j++) {
                    int idx = 32 * j + lane;
                    if (idx < DD * TB) {
                        int b = idx / DD, d = idx - b * DD;
                        xr[j] = xg[b * (TT * DD) + (t + 1) * DD + d];
                    }
                }
            }

            // ================= layer 1 gates =================
            u64t a1[2][4][4];
            #pragma unroll
            for (int g = 0; g < 4; g++) {
                float blo, bhi;
                upk(g == 0 ? bia1_0 : g == 1 ? bia1_1 : g == 2 ? bia1_2 : bia1_3, blo, bhi);
                u64t plo = pk2(blo, blo), phi = pk2(bhi, bhi);
                #pragma unroll
                for (int p = 0; p < 4; p++) { a1[0][g][p] = plo; a1[1][g][p] = phi; }
            }
            #pragma unroll
            for (int d = 0; d < DD; d++) {
                u64t wp[2][4];
                #pragma unroll
                for (int g = 0; g < 4; g++) {
                    u64t wv = lds64(&sW1T[d * G1 + g * H1 + u01]);
                    float wl, wh; upk(wv, wl, wh);
                    wp[0][g] = pk2(wl, wl); wp[1][g] = pk2(wh, wh);
                }
                #pragma unroll
                for (int p = 0; p < 4; p++) {
                    u64t xv = lds64(&sXw[d * XS + 2 * p]);
                    #pragma unroll
                    for (int g = 0; g < 4; g++) {
                        a1[0][g][p] = fma2(wp[0][g], xv, a1[0][g][p]);
                        a1[1][g][p] = fma2(wp[1][g], xv, a1[1][g][p]);
                    }
                }
            }
            #pragma unroll 2
            for (int k = 0; k < H1; k++) {
                u64t wp[2][4];
                #pragma unroll
                for (int g = 0; g < 4; g++) {
                    u64t wv = lds64(&sW1T[(DD + k) * G1 + g * H1 + u01]);
                    float wl, wh; upk(wv, wl, wh);
                    wp[0][g] = pk2(wl, wl); wp[1][g] = pk2(wh, wh);
                }
                #pragma unroll
                for (int p = 0; p < 4; p++) {
                    u64t hv = lds64(&sH1w[k * HS1 + 2 * p]);
                    #pragma unroll
                    for (int g = 0; g < 4; g++) {
                        a1[0][g][p] = fma2(wp[0][g], hv, a1[0][g][p]);
                        a1[1][g][p] = fma2(wp[1][g], hv, a1[1][g][p]);
                    }
                }
            }
            __syncwarp();                      // WAR on old h1

            // pointwise layer1 + write new h1 (HW tanh activations)
            #pragma unroll
            for (int u = 0; u < 2; u++) {
                #pragma unroll
                for (int p = 0; p < 4; p++) {
                    float gi[2], gf[2], gg[2], go[2], hh[2];
                    upk(a1[u][0][p], gi[0], gi[1]);
                    upk(a1[u][1][p], gf[0], gf[1]);
                    upk(a1[u][2][p], gg[0], gg[1]);
                    upk(a1[u][3][p], go[0], go[1]);
                    #pragma unroll
                    for (int s = 0; s < 2; s++) {
                        float ii = siga(gi[s]);
                        float ff = siga(gf[s]);
                        float g_ = tanha(gg[s]);
                        float oo = siga(go[s]);
                        float cc = ff * c1[u][2 * p + s] + ii * g_;
                        c1[u][2 * p + s] = cc;
                        hh[s] = oo * tanha(cc);
                    }
                    sts64(&sH1w[(u01 + u) * HS1 + 2 * p], pk2(hh[0], hh[1]));
                }
            }
            __syncwarp();                      // RAW: new h1 visible

            // ================= layer 2 gates =================
            u64t a2[2][4][2];
            #pragma unroll
            for (int g = 0; g < 4; g++) {
                float blo, bhi;
                upk(g == 0 ? bia2_0 : g == 1 ? bia2_1 : g == 2 ? bia2_2 : bia2_3, blo, bhi);
                u64t plo = pk2(blo, blo), phi = pk2(bhi, bhi);
                #pragma unroll
                for (int p = 0; p < 2; p++) { a2[0][g][p] = plo; a2[1][g][p] = phi; }
            }
            #pragma unroll 2
            for (int k = 0; k < H1; k++) {     // input = new h1
                u64t wp[2][4];
                #pragma unroll
                for (int g = 0; g < 4; g++) {
                    u64t wv = lds64(&sW2T[k * G2 + g * H2 + u02]);
                    float wl, wh; upk(wv, wl, wh);
                    wp[0][g] = pk2(wl, wl); wp[1][g] = pk2(wh, wh);
                }
                #pragma unroll
                for (int p = 0; p < 2; p++) {
                    u64t hv = lds64(&sH1w[k * HS1 + bh2 + 2 * p]);
                    #pragma unroll
                    for (int g = 0; g < 4; g++) {
                        a2[0][g][p] = fma2(wp[0][g], hv, a2[0][g][p]);
                        a2[1][g][p] = fma2(wp[1][g], hv, a2[1][g][p]);
                    }
                }
            }
            #pragma unroll 2
            for (int k = 0; k < H2; k++) {     // recurrent = old h2
                u64t wp[2][4];
                #pragma unroll
                for (int g = 0; g < 4; g++) {
                    u64t wv = lds64(&sW2T[(H1 + k) * G2 + g * H2 + u02]);
                    float wl, wh; upk(wv, wl, wh);
                    wp[0][g] = pk2(wl, wl); wp[1][g] = pk2(wh, wh);
                }
                #pragma unroll
                for (int p = 0; p < 2; p++) {
                    u64t hv = lds64(&sH2w[k * HS2 + bh2 + 2 * p]);
                    #pragma unroll
                    for (int g = 0; g < 4; g++) {
                        a2[0][g][p] = fma2(wp[0][g], hv, a2[0][g][p]);
                        a2[1][g][p] = fma2(wp[1][g], hv, a2[1][g][p]);
                    }
                }
            }
            __syncwarp();                      // WAR on old h2

            // pointwise layer2 + write new h2
            #pragma unroll
            for (int u = 0; u < 2; u++) {
                #pragma unroll
                for (int p = 0; p < 2; p++) {
                    float gi[2], gf[2], gg[2], go[2], hh[2];
                    upk(a2[u][0][p], gi[0], gi[1]);
                    upk(a2[u][1][p], gf[0], gf[1]);
                    upk(a2[u][2][p], gg[0], gg[1]);
                    upk(a2[u][3][p], go[0], go[1]);
                    #pragma unroll
                    for (int s = 0; s < 2; s++) {
                        float ii = siga(gi[s]);
                        float ff = siga(gf[s]);
                        float g_ = tanha(gg[s]);
                        float oo = siga(go[s]);
                        float cc = ff * c2[u][2 * p + s] + ii * g_;
                        c2[u][2 * p + s] = cc;
                        hh[s] = oo * tanha(cc);
                    }
                    sts64(&sH2w[(u02 + u) * HS2 + bh2 + 2 * p], pk2(hh[0], hh[1]));
                }
            }
            __syncwarp();                      // new h2 visible
        }

        // ================= head: dense(16)+relu -> dot(16)+sigmoid =============
        if (lane < TB) {
            const int b = lane;
            float hv[H2];
            #pragma unroll
            for (int k = 0; k < H2; k++) hv[k] = sH2w[k * HS2 + b];
            float o = __ldg(&bo[0]);
            #pragma unroll
            for (int j = 0; j < 16; j++) {
                float s = __ldg(&bd[j]);
                #pragma unroll
                for (int k = 0; k < H2; k++) s += hv[k] * __ldg(&Wd[j * H2 + k]);
                o += fmaxf(s, 0.0f) * __ldg(&Wo[j]);
            }
            out[tau * TB + b] = sigx(o);       // exact sigmoid at output
        }
        __syncwarp();                          // head reads done before next-task zeroing
    }
}

extern "C" void kernel_launch(void* const* d_in, const int* in_sizes, int n_in,
                              void* d_out, int out_size) {
    const float* x    = (const float*)d_in[0];
    const float* Wih1 = (const float*)d_in[1];
    const float* Whh1 = (const float*)d_in[2];
    const float* bih1 = (const float*)d_in[3];
    const float* bhh1 = (const float*)d_in[4];
    const float* Wih2 = (const float*)d_in[5];
    const float* Whh2 = (const float*)d_in[6];
    const float* bih2 = (const float*)d_in[7];
    const float* bhh2 = (const float*)d_in[8];
    const float* Wd   = (const float*)d_in[9];
    const float* bd   = (const float*)d_in[10];
    const float* Wo   = (const float*)d_in[11];
    const float* bo   = (const float*)d_in[12];
    float* out = (float*)d_out;

    static bool attr_set = false;
    if (!attr_set) {
        cudaFuncSetAttribute(momentum_lstm_kernel,
                             cudaFuncAttributeMaxDynamicSharedMemorySize, SMEM_BYTES);
        attr_set = true;
    }

    momentum_lstm_kernel<<<GRID, NT, SMEM_BYTES>>>(
        x, Wih1, Whh1, bih1, bhh1, Wih2, Whh2, bih2, bhh2, Wd, bd, Wo, bo, out);
}